// round 14
// baseline (speedup 1.0000x reference)
#include <cuda_runtime.h>
#include <cuda_fp16.h>
#include <string.h>

// Problem constants
#define B_TOTAL 65536
#define CN 16
#define CC 16
#define DIM 128
#define VOC 65
#define EPSF 1e-5f

// Decomposition: D=128 in 2 chunks of 64. One warp handles TWO rows per
// iteration: lanes 0-15 -> row A, lanes 16-31 -> row B. Each lane owns an
// 8B fp16 slice of its row's 64-wide chunk.
// Table lives in a global fp16 mirror (L1D-cached, 130KB/SM sector footprint).
// Slots UNPACKED (int2 {byte_off, splatted z} -> zero consumer ALU).
// One-iteration software pipeline on the x/v LDGs.
#define DCH 64
#define NCHUNK 2
#define NBX 74            // 74 * 2 = 148 CTAs = one per SM
#define NTHREADS 1024
#define NWARPS 32
#define STEP (2 * NWARPS)

#define EMB_VALS (CC * VOC * DIM)   // 133120 fp16 values = 266240 B mirror

__device__ __half2 d_emb16[EMB_VALS / 2];   // fp16 mirror of emb, full D

// ---- Kernel 0: convert emb fp32 -> fp16 mirror (runs every launch) ----
__global__ void convert_emb_kernel(const float* __restrict__ emb) {
    int i = blockIdx.x * blockDim.x + threadIdx.x;
    if (i < EMB_VALS / 2) {
        float2 f = *(const float2*)(emb + 2 * i);
        d_emb16[i] = __floats2half2_rn(f.x, f.y);
    }
}

__device__ __forceinline__ __half2 u2h2(unsigned u) {
    __half2 h; memcpy(&h, &u, 4); return h;
}

__global__ __launch_bounds__(NTHREADS, 1)
void embed_att_kernel(const float* __restrict__ x_num,
                      const float* __restrict__ means,
                      const float* __restrict__ stds,
                      const float* __restrict__ lin_W,
                      const float* __restrict__ lin_b,
                      const int*   __restrict__ x_cat,
                      float*       __restrict__ out)
{
    // Slot buffers: per warp 2 bufs x 256 B = 512 B -> 16 KB.
    __shared__ __align__(16) char slots[NWARPS * 512];

    const int tid   = threadIdx.x;
    const int lane  = tid & 31;
    const int wrp   = tid >> 5;
    const int sub   = lane & 15;   // attr index (producer) / 8B slice owner
    const int grp   = lane >> 4;   // 0 = row A, 1 = row B
    const int chunk = blockIdx.y;
    const int dbase = chunk * DCH;

    // ---- Per-lane constants (x2 fold for tanh-sigmoid) ----
    const float invr2 = 0.5f / (stds[sub] + EPSF);
    const float c02   = -means[sub] * invr2;
    const int   voff_bytes = sub * VOC * (DIM * 2);   // byte base for attr 'sub'

    // W slice (4 floats per attr) as 2x half2; bias pre-summed in fp32
    __half2 wa[CN], wb[CN];
    float4 bias = make_float4(0.f, 0.f, 0.f, 0.f);
    #pragma unroll
    for (int i = 0; i < CN; i++) {
        float4 wf = *(const float4*)(lin_W + i * DIM + dbase + 4 * sub);
        wa[i] = __floats2half2_rn(wf.x, wf.y);
        wb[i] = __floats2half2_rn(wf.z, wf.w);
        float4 lb = *(const float4*)(lin_b + i * DIM + dbase + 4 * sub);
        bias.x += lb.x; bias.y += lb.y; bias.z += lb.z; bias.w += lb.w;
    }

    // ---- Balanced row range ----
    const int bx    = blockIdx.x;
    const int start = (int)(((long long)bx       * B_TOTAL) / NBX);
    const int end   = (int)(((long long)(bx + 1) * B_TOTAL) / NBX);

    char* wslot = slots + wrp * 512;
    // Lane's gather base inside the fp16 mirror: chunk half + 8B slice.
    const char* myemb = (const char*)d_emb16 + chunk * (DCH * 2) + 8 * sub;
    const int slot_off = (sub >> 1) * 32 + grp * 16 + (sub & 1) * 8;
    int buf = 0;

    const __half2 h2z = __float2half2_rn(0.f);

    int b = start + wrp * 2;

    // ---- Prologue: load + produce iteration 0 into buf 0 ----
    {
        float x = 0.f; int v = 0;
        int r = b + grp;
        if (r < end) {
            x = __ldcs(x_num + r * CN + sub);
            v = __ldcs(x_cat + r * CC + sub);
        }
        float t = fmaf(x, invr2, c02);
        float th;
        asm("tanh.approx.f32 %0, %1;" : "=f"(th) : "f"(t));
        float z = fmaf(th, 0.5f, 0.5f);
        __half2 zz = __float2half2_rn(z);
        int zb; memcpy(&zb, &zz, 4);
        *(int2*)(wslot + slot_off) = make_int2(voff_bytes + v * (DIM * 2), zb);
    }

    for (; b < end; b += STEP) {
        // ---- Issue next iteration's input LDGs (2 live regs; lands during consume) ----
        float xn = 0.f; int vn = 0;
        {
            int nr = b + STEP + grp;
            if (nr < end) {
                xn = __ldcs(x_num + nr * CN + sub);
                vn = __ldcs(x_cat + nr * CC + sub);
            }
        }

        __syncwarp();   // buf's slots (stored last iteration) visible

        // ---- Consume buf: 4 batches of {2 slot LDS.128 -> 4 LDG gathers} ----
        const char* sl = wslot + buf * 256 + grp * 16;
        __half2 a0 = h2z, a1 = h2z, b0h = h2z, b1h = h2z;  // gather chains
        __half2 n0 = h2z, n1 = h2z;                         // numeric chains
        #pragma unroll
        for (int h = 0; h < 4; h++) {
            int4 pA = *(const int4*)(sl + h * 64);        // attrs 4h, 4h+1
            int4 pB = *(const int4*)(sl + h * 64 + 32);   // attrs 4h+2, 4h+3
            uint2 q0 = __ldg((const uint2*)(myemb + pA.x));
            uint2 q1 = __ldg((const uint2*)(myemb + pA.z));
            uint2 q2 = __ldg((const uint2*)(myemb + pB.x));
            uint2 q3 = __ldg((const uint2*)(myemb + pB.z));
            __half2 zh0 = u2h2((unsigned)pA.y);
            __half2 zh1 = u2h2((unsigned)pA.w);
            __half2 zh2 = u2h2((unsigned)pB.y);
            __half2 zh3 = u2h2((unsigned)pB.w);
            // numeric FMA chains (independent of gather results)
            n0 = __hfma2(zh0, wa[4 * h + 0], n0); n1 = __hfma2(zh0, wb[4 * h + 0], n1);
            n0 = __hfma2(zh1, wa[4 * h + 1], n0); n1 = __hfma2(zh1, wb[4 * h + 1], n1);
            n0 = __hfma2(zh2, wa[4 * h + 2], n0); n1 = __hfma2(zh2, wb[4 * h + 2], n1);
            n0 = __hfma2(zh3, wa[4 * h + 3], n0); n1 = __hfma2(zh3, wb[4 * h + 3], n1);
            // gather accumulation: 4 independent chains
            a0  = __hadd2(a0,  u2h2(q0.x)); a1  = __hadd2(a1,  u2h2(q0.y));
            b0h = __hadd2(b0h, u2h2(q1.x)); b1h = __hadd2(b1h, u2h2(q1.y));
            a0  = __hadd2(a0,  u2h2(q2.x)); a1  = __hadd2(a1,  u2h2(q2.y));
            b0h = __hadd2(b0h, u2h2(q3.x)); b1h = __hadd2(b1h, u2h2(q3.y));
        }

        __half2 s0 = __hadd2(__hadd2(a0, b0h), n0);
        __half2 s1 = __hadd2(__hadd2(a1, b1h), n1);
        float2 f0 = __half22float2(s0);
        float2 f1 = __half22float2(s1);
        int myrow = b + grp;
        if (myrow < end) {
            float4 o = make_float4(bias.x + f0.x, bias.y + f0.y,
                                   bias.z + f1.x, bias.w + f1.y);
            __stcs((float4*)(out + (size_t)myrow * DIM + dbase + 4 * sub), o);
        }

        // ---- Produce iteration i+1 into buf^1 (its LDGs already landed) ----
        {
            float t = fmaf(xn, invr2, c02);
            float th;
            asm("tanh.approx.f32 %0, %1;" : "=f"(th) : "f"(t));
            float z = fmaf(th, 0.5f, 0.5f);
            __half2 zz = __float2half2_rn(z);
            int zb; memcpy(&zb, &zz, 4);
            *(int2*)(wslot + (buf ^ 1) * 256 + slot_off) =
                make_int2(voff_bytes + vn * (DIM * 2), zb);
        }
        buf ^= 1;
    }
}

extern "C" void kernel_launch(void* const* d_in, const int* in_sizes, int n_in,
                              void* d_out, int out_size)
{
    const float* x_num = (const float*)d_in[0];
    const float* means = (const float*)d_in[1];
    const float* stds  = (const float*)d_in[2];
    const float* lin_W = (const float*)d_in[3];
    const float* lin_b = (const float*)d_in[4];
    const float* emb   = (const float*)d_in[5];
    const int*   x_cat = (const int*)d_in[6];
    float* out = (float*)d_out;

    // Kernel 0: refresh the fp16 mirror (deterministic, graph-capturable).
    convert_emb_kernel<<<(EMB_VALS / 2 + 255) / 256, 256>>>(emb);

    // Kernel 1: main fused kernel.
    dim3 grid(NBX, NCHUNK);
    embed_att_kernel<<<grid, NTHREADS>>>(
        x_num, means, stds, lin_W, lin_b, x_cat, out);
}

// round 16
// speedup vs baseline: 1.1612x; 1.1612x over previous
#include <cuda_runtime.h>
#include <cuda_fp16.h>
#include <string.h>

// Problem constants
#define B_TOTAL 65536
#define CN 16
#define CC 16
#define DIM 128
#define VOC 65
#define EPSF 1e-5f

// Decomposition: D=128 in 2 chunks of 64. One warp handles TWO rows per
// iteration: lanes 0-15 -> row A, lanes 16-31 -> row B. Each lane owns an
// 8B fp16 slice of its row's 64-wide chunk.
// Table lives in a global fp16 mirror (L1D-cached, 130KB/SM sector footprint).
// Structure identical to the 25.0us R8 kernel; only isolated trims applied:
//   (1) tanh.approx-based sigmoid on the produce path
//   (2) consume loop grouped as 4 batches of 4 LDG gathers (MLP)
#define DCH 64
#define NCHUNK 2
#define NBX 74            // 74 * 2 = 148 CTAs = one per SM
#define NTHREADS 1024
#define NWARPS 32

#define EMB_VALS (CC * VOC * DIM)   // 133120 fp16 values = 266240 B mirror

__device__ __half2 d_emb16[EMB_VALS / 2];   // fp16 mirror of emb, full D

// ---- Kernel 0: convert emb fp32 -> fp16 mirror (runs every launch) ----
__global__ void convert_emb_kernel(const float* __restrict__ emb) {
    int i = blockIdx.x * blockDim.x + threadIdx.x;
    if (i < EMB_VALS / 2) {
        float2 f = *(const float2*)(emb + 2 * i);
        d_emb16[i] = __floats2half2_rn(f.x, f.y);
    }
}

__device__ __forceinline__ __half2 u2h2(unsigned u) {
    __half2 h; memcpy(&h, &u, 4); return h;
}

__global__ __launch_bounds__(NTHREADS, 1)
void embed_att_kernel(const float* __restrict__ x_num,
                      const float* __restrict__ means,
                      const float* __restrict__ stds,
                      const float* __restrict__ lin_W,
                      const float* __restrict__ lin_b,
                      const int*   __restrict__ x_cat,
                      float*       __restrict__ out)
{
    // Slot buffers: per warp 2 bufs x 256 B = 512 B -> 16 KB.
    __shared__ __align__(16) char slots[NWARPS * 512];

    const int tid   = threadIdx.x;
    const int lane  = tid & 31;
    const int wrp   = tid >> 5;
    const int sub   = lane & 15;   // attr index (producer) / 8B slice owner
    const int grp   = lane >> 4;   // 0 = row A, 1 = row B
    const int chunk = blockIdx.y;
    const int dbase = chunk * DCH;

    // ---- Per-lane constants (x2 fold for tanh-based sigmoid) ----
    const float invr2 = 0.5f / (stds[sub] + EPSF);
    const float c02   = -means[sub] * invr2;
    const int   voff_bytes = sub * VOC * (DIM * 2);   // byte base for attr 'sub'

    // W slice (4 floats per attr) as 2x half2; bias pre-summed in fp32
    __half2 wa[CN], wb[CN];
    float4 bias = make_float4(0.f, 0.f, 0.f, 0.f);
    #pragma unroll
    for (int i = 0; i < CN; i++) {
        float4 wf = *(const float4*)(lin_W + i * DIM + dbase + 4 * sub);
        wa[i] = __floats2half2_rn(wf.x, wf.y);
        wb[i] = __floats2half2_rn(wf.z, wf.w);
        float4 lb = *(const float4*)(lin_b + i * DIM + dbase + 4 * sub);
        bias.x += lb.x; bias.y += lb.y; bias.z += lb.z; bias.w += lb.w;
    }

    // ---- Balanced row range ----
    const int bx    = blockIdx.x;
    const int start = (int)(((long long)bx       * B_TOTAL) / NBX);
    const int end   = (int)(((long long)(bx + 1) * B_TOTAL) / NBX);

    char* wslot = slots + wrp * 512;
    // Lane's gather base inside the fp16 mirror: chunk half + 8B slice.
    const char* myemb = (const char*)d_emb16 + chunk * (DCH * 2) + 8 * sub;
    const int slot_off = (sub >> 1) * 32 + grp * 16 + (sub & 1) * 8;
    int buf = 0;

    const __half2 h2z = __float2half2_rn(0.f);

    for (int b = start + wrp * 2; b < end; b += 2 * NWARPS) {
        const int  myrow = b + grp;
        const bool valid = myrow < end;

        // ---- Produce: {gather byte offset, z} for (myrow, sub) ----
        float x = 0.f; int v = 0;
        if (valid) {
            x = __ldcs(x_num + myrow * CN + sub);
            v = __ldcs(x_cat + myrow * CC + sub);
        }
        // sigmoid(t) = 0.5*tanh(t/2)+0.5, with the 1/2 folded into invr2/c02
        float t = fmaf(x, invr2, c02);
        float th;
        asm("tanh.approx.f32 %0, %1;" : "=f"(th) : "f"(t));
        float z = fmaf(th, 0.5f, 0.5f);
        __half2 zz = __float2half2_rn(z);
        int zb; memcpy(&zb, &zz, 4);
        *(int2*)(wslot + buf * 256 + slot_off) =
            make_int2(voff_bytes + v * (DIM * 2), zb);
        __syncwarp();

        // ---- Consume: 4 batches of {2 slot LDS.128 -> 4 LDG gathers} ----
        const char* sl = wslot + buf * 256 + grp * 16;
        __half2 a0 = h2z, a1 = h2z, b0h = h2z, b1h = h2z;  // gather chains
        __half2 n0 = h2z, n1 = h2z;                         // numeric chains
        #pragma unroll
        for (int h = 0; h < 4; h++) {
            int4 pA = *(const int4*)(sl + h * 64);        // attrs 4h, 4h+1
            int4 pB = *(const int4*)(sl + h * 64 + 32);   // attrs 4h+2, 4h+3
            uint2 q0 = __ldg((const uint2*)(myemb + pA.x));
            uint2 q1 = __ldg((const uint2*)(myemb + pA.z));
            uint2 q2 = __ldg((const uint2*)(myemb + pB.x));
            uint2 q3 = __ldg((const uint2*)(myemb + pB.z));
            __half2 zh0 = u2h2((unsigned)pA.y);
            __half2 zh1 = u2h2((unsigned)pA.w);
            __half2 zh2 = u2h2((unsigned)pB.y);
            __half2 zh3 = u2h2((unsigned)pB.w);
            // numeric FMA chains (independent of gather results)
            n0 = __hfma2(zh0, wa[4 * h + 0], n0); n1 = __hfma2(zh0, wb[4 * h + 0], n1);
            n0 = __hfma2(zh1, wa[4 * h + 1], n0); n1 = __hfma2(zh1, wb[4 * h + 1], n1);
            n0 = __hfma2(zh2, wa[4 * h + 2], n0); n1 = __hfma2(zh2, wb[4 * h + 2], n1);
            n0 = __hfma2(zh3, wa[4 * h + 3], n0); n1 = __hfma2(zh3, wb[4 * h + 3], n1);
            // gather accumulation: 4 independent chains
            a0  = __hadd2(a0,  u2h2(q0.x)); a1  = __hadd2(a1,  u2h2(q0.y));
            b0h = __hadd2(b0h, u2h2(q1.x)); b1h = __hadd2(b1h, u2h2(q1.y));
            a0  = __hadd2(a0,  u2h2(q2.x)); a1  = __hadd2(a1,  u2h2(q2.y));
            b0h = __hadd2(b0h, u2h2(q3.x)); b1h = __hadd2(b1h, u2h2(q3.y));
        }

        __half2 s0 = __hadd2(__hadd2(a0, b0h), n0);
        __half2 s1 = __hadd2(__hadd2(a1, b1h), n1);
        float2 f0 = __half22float2(s0);
        float2 f1 = __half22float2(s1);
        if (valid) {
            float4 o = make_float4(bias.x + f0.x, bias.y + f0.y,
                                   bias.z + f1.x, bias.w + f1.y);
            __stcs((float4*)(out + (size_t)myrow * DIM + dbase + 4 * sub), o);
        }
        buf ^= 1;
    }
}

extern "C" void kernel_launch(void* const* d_in, const int* in_sizes, int n_in,
                              void* d_out, int out_size)
{
    const float* x_num = (const float*)d_in[0];
    const float* means = (const float*)d_in[1];
    const float* stds  = (const float*)d_in[2];
    const float* lin_W = (const float*)d_in[3];
    const float* lin_b = (const float*)d_in[4];
    const float* emb   = (const float*)d_in[5];
    const int*   x_cat = (const int*)d_in[6];
    float* out = (float*)d_out;

    // Kernel 0: refresh the fp16 mirror (deterministic, graph-capturable).
    convert_emb_kernel<<<(EMB_VALS / 2 + 255) / 256, 256>>>(emb);

    // Kernel 1: main fused kernel.
    dim3 grid(NBX, NCHUNK);
    embed_att_kernel<<<grid, NTHREADS>>>(
        x_num, means, stds, lin_W, lin_b, x_cat, out);
}